// round 13
// baseline (speedup 1.0000x reference)
#include <cuda_runtime.h>
#include <cstdint>

// ---------------------------------------------------------------------------
// Attention2D — Round 13 (third submit of the multi-kernel split; R11/R12
// both died to broker container failures with zero signal — same flake
// pattern as R6/R7 before R8 ran this exact strategy's predecessor).
//   prep:  Ws2 = Ws@Ws ; tf32 hi/lo splits of Ws/Ws2/Wo packed as uint2
//   K1:    q_ = q@Ws          (3xTF32 GEMM, 32-row CTAs)  -> g_qp
//   fused: dual GEMM + pos/attn MLPs + softmax (E0/E6 evicted) -> g_y
//   K3:    x = y@Wo + bo      (3xTF32 GEMM)               -> out
// ---------------------------------------------------------------------------

#define CDIM    256
#define HIDD    32
#define MTOK    16
#define TPC     2                    // tokens per CTA (fused)
#define RPC     32                   // rows per CTA (fused & gemm)
#define SKS     260                  // result smem row stride
#define AST     264                  // A-stage row stride
#define HS      36
#define NTOK    16384
#define NTHR    512
#define NKSTEP  (CDIM / 8)

#define BIGF    (2 * RPC * SKS)
#define SMEM_FLOATS (BIGF + RPC*HS + TPC*SKS + RPC*4 + RPC)
#define SMEM_BYTES  (SMEM_FLOATS * 4)

__device__ float g_Ws2[CDIM * CDIM];
__device__ uint2 g_WsSpl [CDIM * CDIM];   // (tf32_hi, tf32_lo) of Ws
__device__ uint2 g_Ws2Spl[CDIM * CDIM];   // of Ws2
__device__ uint2 g_WoSpl [CDIM * CDIM];   // of Wo
__device__ float g_qp[(long)NTOK * CDIM]; // q @ Ws
__device__ float g_y [(long)NTOK * CDIM]; // pooled output before Wo

__device__ __forceinline__ uint32_t f2tf32(float x) {
    uint32_t r;
    asm("cvt.rna.tf32.f32 %0, %1;" : "=r"(r) : "f"(x));
    return r;
}

__device__ __forceinline__ void mma8(float* d, const uint32_t* a,
                                     uint32_t b0, uint32_t b1) {
    asm volatile(
        "mma.sync.aligned.m16n8k8.row.col.f32.tf32.tf32.f32 "
        "{%0,%1,%2,%3}, {%4,%5,%6,%7}, {%8,%9}, {%0,%1,%2,%3};"
        : "+f"(d[0]), "+f"(d[1]), "+f"(d[2]), "+f"(d[3])
        : "r"(a[0]), "r"(a[1]), "r"(a[2]), "r"(a[3]), "r"(b0), "r"(b1));
}

// ---------------------------------------------------------------------------
__global__ void ws2_kernel(const float* __restrict__ Ws) {
    __shared__ float row[CDIM];
    const int r = blockIdx.x, c = threadIdx.x;
    row[c] = Ws[r * CDIM + c];
    __syncthreads();
    float acc = 0.f;
#pragma unroll 8
    for (int kk = 0; kk < CDIM; kk++)
        acc = fmaf(row[kk], __ldg(Ws + kk * CDIM + c), acc);
    g_Ws2[r * CDIM + c] = acc;
}

// tf32 hi/lo splits of Ws, Ws2, Wo (runs AFTER ws2_kernel; same stream)
__global__ void split_kernel(const float* __restrict__ Ws,
                             const float* __restrict__ Wo) {
    const int i = blockIdx.x * 256 + threadIdx.x;
    float a = __ldg(Ws + i);
    uint32_t h = f2tf32(a);
    g_WsSpl[i] = make_uint2(h, f2tf32(a - __uint_as_float(h)));
    float b = g_Ws2[i];
    h = f2tf32(b);
    g_Ws2Spl[i] = make_uint2(h, f2tf32(b - __uint_as_float(h)));
    float c = __ldg(Wo + i);
    h = f2tf32(c);
    g_WoSpl[i] = make_uint2(h, f2tf32(c - __uint_as_float(h)));
}

// ---------------------------------------------------------------------------
// Generic 3xTF32 GEMM, 32 rows/CTA, C[16384x256] = A @ B (+bias).
// mode 0: A=Aext(q), B=g_WsSpl, C=g_qp, no bias.
// mode 1: A=g_y,     B=g_WoSpl, C=Cext(out), bias=bo.
// ---------------------------------------------------------------------------
__global__ __launch_bounds__(NTHR, 2)
void gemm32_kernel(const float* __restrict__ Aext,
                   const float* __restrict__ bias,
                   float* __restrict__ Cext, int mode)
{
    __shared__ float smA[RPC * AST];             // 33,792 B
    const float* A = (mode == 0) ? Aext : g_y;
    float*       C = (mode == 0) ? g_qp : Cext;
    const uint2* B = (mode == 0) ? g_WsSpl : g_WoSpl;

    const int tid = threadIdx.x;
    const long r0 = (long)blockIdx.x * RPC;

    // stage A k-permuted (k%8: 0..3 -> even slots, 4..7 -> odd)
#pragma unroll
    for (int rep = 0; rep < 4; rep++) {
        const int idx = tid + rep * NTHR;
        const int m = idx >> 6, c4 = idx & 63;
        float4 v = __ldg((const float4*)(A + (r0 + m) * CDIM) + c4);
        const int kk  = c4 * 4;
        const int off = m * AST + (kk & ~7) + ((kk & 4) ? 1 : 0);
        smA[off + 0] = v.x;
        smA[off + 2] = v.y;
        smA[off + 4] = v.z;
        smA[off + 6] = v.w;
    }
    __syncthreads();

    const int wid = tid >> 5, lane = tid & 31;
    const int gid = lane >> 2, tig = lane & 3;
    const int rb  = (wid >> 3) * 16;     // row half: 0 or 16
    const int ncb = (wid & 7) * 32;      // 32-col block

    float d[4][4];
#pragma unroll
    for (int ni = 0; ni < 4; ni++)
#pragma unroll
        for (int c = 0; c < 4; c++) d[ni][c] = 0.f;

    for (int ks = 0; ks < NKSTEP; ks++) {
        const int k0 = ks * 8;
        const float2 p0 = *(const float2*)(smA + (rb + gid) * AST + k0 + tig * 2);
        const float2 p1 = *(const float2*)(smA + (rb + gid + 8) * AST + k0 + tig * 2);
        uint32_t ah[4], al[4];
        ah[0] = f2tf32(p0.x); al[0] = f2tf32(p0.x - __uint_as_float(ah[0]));
        ah[1] = f2tf32(p1.x); al[1] = f2tf32(p1.x - __uint_as_float(ah[1]));
        ah[2] = f2tf32(p0.y); al[2] = f2tf32(p0.y - __uint_as_float(ah[2]));
        ah[3] = f2tf32(p1.y); al[3] = f2tf32(p1.y - __uint_as_float(ah[3]));
#pragma unroll
        for (int ni = 0; ni < 4; ni++) {
            const int bc = ncb + ni * 8 + gid;
            const uint2 u0 = __ldg(B + (k0 + tig)     * CDIM + bc);
            const uint2 u1 = __ldg(B + (k0 + tig + 4) * CDIM + bc);
            mma8(d[ni], ah, u0.x, u1.x);   // hi*hi
            mma8(d[ni], al, u0.x, u1.x);   // lo*hi
            mma8(d[ni], ah, u0.y, u1.y);   // hi*lo
        }
    }

#pragma unroll
    for (int ni = 0; ni < 4; ni++) {
        const int c0 = ncb + ni * 8 + 2 * tig;
        float2 v01 = make_float2(d[ni][0], d[ni][1]);
        float2 v23 = make_float2(d[ni][2], d[ni][3]);
        if (mode == 1) {
            const float2 bv = *(const float2*)(bias + c0);
            v01.x += bv.x; v01.y += bv.y;
            v23.x += bv.x; v23.y += bv.y;
        }
        *(float2*)(C + (r0 + rb + gid)     * CDIM + c0) = v01;
        *(float2*)(C + (r0 + rb + gid + 8) * CDIM + c0) = v23;
    }
}

// ---------------------------------------------------------------------------
// Fused kernel: dual GEMM + E1-E5 (E0/E6 evicted). Writes y to g_y.
// ---------------------------------------------------------------------------
__global__ __launch_bounds__(NTHR, 2)
void fused_kernel(const float* __restrict__ k,
                  const float* __restrict__ pos, const int* __restrict__ mask,
                  const float* __restrict__ Wp1, const float* __restrict__ bp1,
                  const float* __restrict__ Wp2, const float* __restrict__ bp2,
                  const float* __restrict__ Wa1, const float* __restrict__ ba1,
                  const float* __restrict__ Wa2, const float* __restrict__ ba2)
{
    extern __shared__ float sm[];
    float* sm_big  = sm;                         // A-stage -> s1/ai/logits
    float* sm_res2 = sm_big + RPC * SKS;         // s2 -> vv
    float* sm_h    = sm_big + BIGF;              // pos hidden -> attn hidden
    float* sm_qp   = sm_h   + RPC * HS;          // q_ rows (from g_qp)
    float* sm_pos  = sm_qp  + TPC * SKS;
    int*   sm_mask = (int*)(sm_pos + RPC * 4);

    const int tid = threadIdx.x;
    const int tq  = blockIdx.x * TPC;
    const int r0g = tq * MTOK;

    // ---- stage: k rows k-permuted; q_ rows; pos; mask ---------------------
    {
        const float* kp = k + (long)r0g * CDIM;
#pragma unroll
        for (int rep = 0; rep < 4; rep++) {
            const int idx = tid + rep * NTHR;          // RPC*64 = 2048
            const int m = idx >> 6, c4 = idx & 63;
            float4 v = __ldg((const float4*)(kp + m * CDIM) + c4);
            const int kk  = c4 * 4;
            const int off = m * AST + (kk & ~7) + ((kk & 4) ? 1 : 0);
            sm_big[off + 0] = v.x;
            sm_big[off + 2] = v.y;
            sm_big[off + 4] = v.z;
            sm_big[off + 6] = v.w;
        }
        if (tid < TPC * 64) {
            const int t = tid >> 6, c4 = tid & 63;
            float4 v = *(const float4*)(g_qp + (long)(tq + t) * CDIM + c4 * 4);
            *(float4*)(sm_qp + t * SKS + c4 * 4) = v;
        }
        if (tid < RPC) {
            float4 pv = __ldg((const float4*)pos + (r0g + tid));
            *(float4*)(sm_pos + tid * 4) = pv;
            sm_mask[tid] = __ldg(mask + r0g + tid);
        }
    }
    __syncthreads();

    // ---- dual GEMM (3xTF32, presplit B): s1 = k@Ws, s2 = k@Ws2 ------------
    {
        const int wid  = tid >> 5, lane = tid & 31;
        const int gid  = lane >> 2, tig = lane & 3;
        const uint2* Bspl = (wid < 8) ? g_WsSpl : g_Ws2Spl;
        const int ncb = (wid & 7) * 32;

        float d[2][4][4];
#pragma unroll
        for (int mi = 0; mi < 2; mi++)
#pragma unroll
            for (int ni = 0; ni < 4; ni++)
#pragma unroll
                for (int c = 0; c < 4; c++) d[mi][ni][c] = 0.f;

        for (int ks = 0; ks < NKSTEP; ks++) {
            const int k0 = ks * 8;
            uint32_t bh0[4], bh1[4], bl0[4], bl1[4];
#pragma unroll
            for (int ni = 0; ni < 4; ni++) {
                const int bc = ncb + ni * 8 + gid;
                const uint2 u0 = __ldg(Bspl + (k0 + tig)     * CDIM + bc);
                const uint2 u1 = __ldg(Bspl + (k0 + tig + 4) * CDIM + bc);
                bh0[ni] = u0.x; bl0[ni] = u0.y;
                bh1[ni] = u1.x; bl1[ni] = u1.y;
            }
#pragma unroll
            for (int mi = 0; mi < 2; mi++) {
                const float2 p0 = *(const float2*)(sm_big + (mi * 16 + gid) * AST + k0 + tig * 2);
                const float2 p1 = *(const float2*)(sm_big + (mi * 16 + gid + 8) * AST + k0 + tig * 2);
                uint32_t ah[4], al[4];
                ah[0] = f2tf32(p0.x); al[0] = f2tf32(p0.x - __uint_as_float(ah[0]));
                ah[1] = f2tf32(p1.x); al[1] = f2tf32(p1.x - __uint_as_float(ah[1]));
                ah[2] = f2tf32(p0.y); al[2] = f2tf32(p0.y - __uint_as_float(ah[2]));
                ah[3] = f2tf32(p1.y); al[3] = f2tf32(p1.y - __uint_as_float(ah[3]));
#pragma unroll
                for (int ni = 0; ni < 4; ni++) {
                    mma8(d[mi][ni], ah, bh0[ni], bh1[ni]);   // hi*hi
                    mma8(d[mi][ni], al, bh0[ni], bh1[ni]);   // lo*hi
                    mma8(d[mi][ni], ah, bl0[ni], bl1[ni]);   // hi*lo
                }
            }
        }
        __syncthreads();                 // A-stage dead; results may overwrite
        float* dst = (wid < 8) ? sm_big : sm_res2;
#pragma unroll
        for (int mi = 0; mi < 2; mi++)
#pragma unroll
            for (int ni = 0; ni < 4; ni++) {
                const int r0 = mi * 16 + gid;
                const int c0 = ncb + ni * 8 + 2 * tig;
                *(float2*)&dst[r0 * SKS + c0]       = make_float2(d[mi][ni][0], d[mi][ni][1]);
                *(float2*)&dst[(r0 + 8) * SKS + c0] = make_float2(d[mi][ni][2], d[mi][ni][3]);
            }
    }
    __syncthreads();

    const int cg = tid & 63;
    const int rg = tid >> 6;             // 0..7, 4 rows each

    // ---- E1: pos hidden ----------------------------------------------------
    {
        const int m  = tid >> 4;             // 0..31
        const int j2 = (tid & 15) * 2;
        const float p0 = sm_pos[m * 4 + 0], p1 = sm_pos[m * 4 + 1];
        const float p2 = sm_pos[m * 4 + 2], p3 = sm_pos[m * 4 + 3];
#pragma unroll
        for (int u = 0; u < 2; u++) {
            const int j = j2 + u;
            float h = __ldg(bp1 + j);
            h = fmaf(p0, __ldg(Wp1 +  0 + j), h);
            h = fmaf(p1, __ldg(Wp1 + 32 + j), h);
            h = fmaf(p2, __ldg(Wp1 + 64 + j), h);
            h = fmaf(p3, __ldg(Wp1 + 96 + j), h);
            sm_h[m * HS + j] = fmaxf(h, 0.f);
        }
    }
    __syncthreads();

    // ---- E2 (interchanged): posf for 4 rows, Wp2 loaded once per j --------
    {
        const int tokl = rg >> 2;
        const float qp0 = sm_qp[tokl * SKS + cg * 4 + 0];
        const float qp1 = sm_qp[tokl * SKS + cg * 4 + 1];
        const float qp2 = sm_qp[tokl * SKS + cg * 4 + 2];
        const float qp3 = sm_qp[tokl * SKS + cg * 4 + 3];
        const float4 b2 = __ldg((const float4*)(bp2 + cg * 4));
        float4 pf[4];
#pragma unroll
        for (int i = 0; i < 4; i++) pf[i] = b2;
        const float* hbase = sm_h + (rg * 4) * HS;
#pragma unroll 4
        for (int j = 0; j < HIDD; j++) {
            const float4 w = __ldg((const float4*)(Wp2 + j * CDIM + cg * 4));
#pragma unroll
            for (int i = 0; i < 4; i++) {
                const float hv = hbase[i * HS + j];
                pf[i].x = fmaf(hv, w.x, pf[i].x);
                pf[i].y = fmaf(hv, w.y, pf[i].y);
                pf[i].z = fmaf(hv, w.z, pf[i].z);
                pf[i].w = fmaf(hv, w.w, pf[i].w);
            }
        }
#pragma unroll
        for (int i = 0; i < 4; i++) {
            const int m = rg * 4 + i;
            float4 s1v = *(const float4*)(sm_big  + m * SKS + cg * 4);
            float4 s2v = *(const float4*)(sm_res2 + m * SKS + cg * 4);
            float4 ai, vv;
            ai.x = s1v.x - qp0 + pf[i].x;  vv.x = s2v.x + pf[i].x;
            ai.y = s1v.y - qp1 + pf[i].y;  vv.y = s2v.y + pf[i].y;
            ai.z = s1v.z - qp2 + pf[i].z;  vv.z = s2v.z + pf[i].z;
            ai.w = s1v.w - qp3 + pf[i].w;  vv.w = s2v.w + pf[i].w;
            *(float4*)(sm_big  + m * SKS + cg * 4) = ai;
            *(float4*)(sm_res2 + m * SKS + cg * 4) = vv;
        }
    }
    __syncthreads();

    // ---- E3: h2 = relu(ai @ Wa1 + ba1) ------------------------------------
    {
        const int m  = tid >> 4;             // 0..31
        const int jp = (tid & 15) * 2;
        float2 acc = *(const float2*)(ba1 + jp);
        const float* as = sm_big + m * SKS;
#pragma unroll 4
        for (int c2 = 0; c2 < CDIM; c2++) {
            const float a = as[c2];
            const float2 w = __ldg((const float2*)(Wa1 + c2 * HIDD + jp));
            acc.x = fmaf(a, w.x, acc.x);
            acc.y = fmaf(a, w.y, acc.y);
        }
        acc.x = fmaxf(acc.x, 0.f);
        acc.y = fmaxf(acc.y, 0.f);
        *(float2*)(sm_h + m * HS + jp) = acc;
    }
    __syncthreads();

    // ---- E4 (interchanged): logits for 4 rows, Wa2 loaded once per j ------
    {
        const float4 b2 = __ldg((const float4*)(ba2 + cg * 4));
        float4 acc[4];
#pragma unroll
        for (int i = 0; i < 4; i++) acc[i] = b2;
        const float* hbase = sm_h + (rg * 4) * HS;
#pragma unroll 4
        for (int j = 0; j < HIDD; j++) {
            const float4 w = __ldg((const float4*)(Wa2 + j * CDIM + cg * 4));
#pragma unroll
            for (int i = 0; i < 4; i++) {
                const float hv = hbase[i * HS + j];
                acc[i].x = fmaf(hv, w.x, acc[i].x);
                acc[i].y = fmaf(hv, w.y, acc[i].y);
                acc[i].z = fmaf(hv, w.z, acc[i].z);
                acc[i].w = fmaf(hv, w.w, acc[i].w);
            }
        }
#pragma unroll
        for (int i = 0; i < 4; i++) {
            const int m = rg * 4 + i;
            float4 v = acc[i];
            if (sm_mask[m] == 0) { v.x = -1e9f; v.y = -1e9f; v.z = -1e9f; v.w = -1e9f; }
            *(float4*)(sm_big + m * SKS + cg * 4) = v;
        }
    }
    __syncthreads();

    // ---- E5: softmax over M, weighted sum -> g_y (global) -----------------
    {
        const int t = tid >> 8, c = tid & 255;
        const float* lp  = sm_big  + (t * MTOK) * SKS + c;
        const float* vpp = sm_res2 + (t * MTOK) * SKS + c;
        float mx = -3.4e38f;
#pragma unroll
        for (int m = 0; m < MTOK; m++) mx = fmaxf(mx, lp[m * SKS]);
        float s = 0.f, acc = 0.f;
#pragma unroll
        for (int m = 0; m < MTOK; m++) {
            const float e = __expf(lp[m * SKS] - mx);
            s += e;
            acc = fmaf(e, vpp[m * SKS], acc);
        }
        g_y[(long)(tq + t) * CDIM + c] = acc / s;
    }
}

// ---------------------------------------------------------------------------
extern "C" void kernel_launch(void* const* d_in, const int* in_sizes, int n_in,
                              void* d_out, int out_size) {
    const float* q   = (const float*)d_in[0];
    const float* k   = (const float*)d_in[1];
    const float* pos = (const float*)d_in[2];
    const int*   mask= (const int*)  d_in[3];
    const float* Ws  = (const float*)d_in[4];
    const float* Wp1 = (const float*)d_in[5];
    const float* bp1 = (const float*)d_in[6];
    const float* Wp2 = (const float*)d_in[7];
    const float* bp2 = (const float*)d_in[8];
    const float* Wa1 = (const float*)d_in[9];
    const float* ba1 = (const float*)d_in[10];
    const float* Wa2 = (const float*)d_in[11];
    const float* ba2 = (const float*)d_in[12];
    const float* Wo  = (const float*)d_in[13];
    const float* bo  = (const float*)d_in[14];
    float* out = (float*)d_out;

    cudaFuncSetAttribute(fused_kernel,
                         cudaFuncAttributeMaxDynamicSharedMemorySize, SMEM_BYTES);

    ws2_kernel  <<<CDIM, CDIM>>>(Ws);
    split_kernel<<<CDIM, CDIM>>>(Ws, Wo);
    gemm32_kernel<<<NTOK / RPC, NTHR>>>(q, nullptr, nullptr, 0);     // q_ = q@Ws
    fused_kernel<<<NTOK / TPC, NTHR, SMEM_BYTES>>>(
        k, pos, mask, Wp1, bp1, Wp2, bp2, Wa1, ba1, Wa2, ba2);
    gemm32_kernel<<<NTOK / RPC, NTHR>>>(nullptr, bo, out, 1);        // x = y@Wo + bo
}

// round 14
// speedup vs baseline: 1.3449x; 1.3449x over previous
#include <cuda_runtime.h>
#include <cstdint>

// ---------------------------------------------------------------------------
// Attention2D — Round 14: fragment-ordered B operands.
//   prep:  Ws2 = Ws@Ws ; Ws/Ws2/Wo stored as mma-fragment-ordered uint4
//          {hi_r1, hi_r2, lo_r1, lo_r2} so a warp's B load is 512B contiguous
//          (4 wavefronts @100% vs 16 @25% for the strided layout).
//   K1:    q_ = q@Ws          (3xTF32 GEMM, 32-row CTAs)  -> g_qp
//   fused: dual GEMM + pos/attn MLPs + softmax -> g_y
//   K3:    x = y@Wo + bo      (3xTF32 GEMM)               -> out
// A-side: raw fp32 k-permuted smem + register tf32 split (proven R10 path).
// ---------------------------------------------------------------------------

#define CDIM    256
#define HIDD    32
#define MTOK    16
#define TPC     2                    // tokens per CTA (fused)
#define RPC     32                   // rows per CTA (fused & gemm)
#define SKS     260                  // result smem row stride
#define AST     264                  // A-stage row stride
#define HS      36
#define NTOK    16384
#define NTHR    512
#define NKSTEP  (CDIM / 8)
#define NFRAG   (NKSTEP * CDIM * 4)  // 32768 uint4 entries per matrix

#define BIGF    (2 * RPC * SKS)
#define SMEM_FLOATS (BIGF + RPC*HS + TPC*SKS + RPC*4 + RPC)
#define SMEM_BYTES  (SMEM_FLOATS * 4)

__device__ float g_Ws2[CDIM * CDIM];
__device__ uint4 g_WsFrag [NFRAG];        // fragment-ordered Ws  (tf32 hi/lo)
__device__ uint4 g_Ws2Frag[NFRAG];        // fragment-ordered Ws2
__device__ uint4 g_WoFrag [NFRAG];        // fragment-ordered Wo
__device__ float g_qp[(long)NTOK * CDIM]; // q @ Ws
__device__ float g_y [(long)NTOK * CDIM]; // pooled output before Wo

__device__ __forceinline__ uint32_t f2tf32(float x) {
    uint32_t r;
    asm("cvt.rna.tf32.f32 %0, %1;" : "=r"(r) : "f"(x));
    return r;
}

__device__ __forceinline__ void mma8(float* d, const uint32_t* a,
                                     uint32_t b0, uint32_t b1) {
    asm volatile(
        "mma.sync.aligned.m16n8k8.row.col.f32.tf32.tf32.f32 "
        "{%0,%1,%2,%3}, {%4,%5,%6,%7}, {%8,%9}, {%0,%1,%2,%3};"
        : "+f"(d[0]), "+f"(d[1]), "+f"(d[2]), "+f"(d[3])
        : "r"(a[0]), "r"(a[1]), "r"(a[2]), "r"(a[3]), "r"(b0), "r"(b1));
}

// ---------------------------------------------------------------------------
__global__ void ws2_kernel(const float* __restrict__ Ws) {
    __shared__ float row[CDIM];
    const int r = blockIdx.x, c = threadIdx.x;
    row[c] = Ws[r * CDIM + c];
    __syncthreads();
    float acc = 0.f;
#pragma unroll 8
    for (int kk = 0; kk < CDIM; kk++)
        acc = fmaf(row[kk], __ldg(Ws + kk * CDIM + c), acc);
    g_Ws2[r * CDIM + c] = acc;
}

// Build fragment-ordered hi/lo arrays for Ws, Ws2, Wo. (AFTER ws2_kernel.)
// Entry (ks, c, tig) holds rows r1 = ks*8+tig, r2 = r1+4 of column c:
//   uint4{ hi(B[r1][c]), hi(B[r2][c]), lo(B[r1][c]), lo(B[r2][c]) }
__global__ void frag_kernel(const float* __restrict__ Ws,
                            const float* __restrict__ Wo) {
    const int i   = blockIdx.x * 256 + threadIdx.x;     // 0 .. 32767
    const int ks  = i >> 10;
    const int c   = (i >> 2) & 255;
    const int tig = i & 3;
    const int r1  = ks * 8 + tig, r2 = r1 + 4;

    float a1 = __ldg(Ws + r1 * CDIM + c), a2 = __ldg(Ws + r2 * CDIM + c);
    uint32_t h1 = f2tf32(a1), h2 = f2tf32(a2);
    g_WsFrag[i] = make_uint4(h1, h2, f2tf32(a1 - __uint_as_float(h1)),
                                     f2tf32(a2 - __uint_as_float(h2)));
    a1 = g_Ws2[r1 * CDIM + c]; a2 = g_Ws2[r2 * CDIM + c];
    h1 = f2tf32(a1); h2 = f2tf32(a2);
    g_Ws2Frag[i] = make_uint4(h1, h2, f2tf32(a1 - __uint_as_float(h1)),
                                      f2tf32(a2 - __uint_as_float(h2)));
    a1 = __ldg(Wo + r1 * CDIM + c); a2 = __ldg(Wo + r2 * CDIM + c);
    h1 = f2tf32(a1); h2 = f2tf32(a2);
    g_WoFrag[i] = make_uint4(h1, h2, f2tf32(a1 - __uint_as_float(h1)),
                                     f2tf32(a2 - __uint_as_float(h2)));
}

// ---------------------------------------------------------------------------
// Generic 3xTF32 GEMM, 32 rows/CTA, C[16384x256] = A @ B (+bias).
// mode 0: A=Aext(q), B=g_WsFrag, C=g_qp, no bias.
// mode 1: A=g_y,     B=g_WoFrag, C=Cext(out), bias=bo.
// ---------------------------------------------------------------------------
__global__ __launch_bounds__(NTHR, 2)
void gemm32_kernel(const float* __restrict__ Aext,
                   const float* __restrict__ bias,
                   float* __restrict__ Cext, int mode)
{
    __shared__ float smA[RPC * AST];             // 33,792 B
    const float* A  = (mode == 0) ? Aext : g_y;
    float*       C  = (mode == 0) ? g_qp : Cext;
    const uint4* Bf = (mode == 0) ? g_WsFrag : g_WoFrag;

    const int tid = threadIdx.x;
    const long r0 = (long)blockIdx.x * RPC;

    // stage A k-permuted (k%8: 0..3 -> even slots, 4..7 -> odd)
#pragma unroll
    for (int rep = 0; rep < 4; rep++) {
        const int idx = tid + rep * NTHR;
        const int m = idx >> 6, c4 = idx & 63;
        float4 v = __ldg((const float4*)(A + (r0 + m) * CDIM) + c4);
        const int kk  = c4 * 4;
        const int off = m * AST + (kk & ~7) + ((kk & 4) ? 1 : 0);
        smA[off + 0] = v.x;
        smA[off + 2] = v.y;
        smA[off + 4] = v.z;
        smA[off + 6] = v.w;
    }
    __syncthreads();

    const int wid = tid >> 5, lane = tid & 31;
    const int gid = lane >> 2, tig = lane & 3;
    const int rb  = (wid >> 3) * 16;     // row half: 0 or 16
    const int ncb = (wid & 7) * 32;      // 32-col block

    float d[4][4];
#pragma unroll
    for (int ni = 0; ni < 4; ni++)
#pragma unroll
        for (int c = 0; c < 4; c++) d[ni][c] = 0.f;

    for (int ks = 0; ks < NKSTEP; ks++) {
        const int k0 = ks * 8;
        const float2 p0 = *(const float2*)(smA + (rb + gid) * AST + k0 + tig * 2);
        const float2 p1 = *(const float2*)(smA + (rb + gid + 8) * AST + k0 + tig * 2);
        uint32_t ah[4], al[4];
        ah[0] = f2tf32(p0.x); al[0] = f2tf32(p0.x - __uint_as_float(ah[0]));
        ah[1] = f2tf32(p1.x); al[1] = f2tf32(p1.x - __uint_as_float(ah[1]));
        ah[2] = f2tf32(p0.y); al[2] = f2tf32(p0.y - __uint_as_float(ah[2]));
        ah[3] = f2tf32(p1.y); al[3] = f2tf32(p1.y - __uint_as_float(ah[3]));
#pragma unroll
        for (int ni = 0; ni < 4; ni++) {
            const uint4 u = __ldg(Bf + ((ks * CDIM + ncb + ni * 8 + gid) << 2) + tig);
            mma8(d[ni], ah, u.x, u.y);   // hi*hi
            mma8(d[ni], al, u.x, u.y);   // lo*hi
            mma8(d[ni], ah, u.z, u.w);   // hi*lo
        }
    }

#pragma unroll
    for (int ni = 0; ni < 4; ni++) {
        const int c0 = ncb + ni * 8 + 2 * tig;
        float2 v01 = make_float2(d[ni][0], d[ni][1]);
        float2 v23 = make_float2(d[ni][2], d[ni][3]);
        if (mode == 1) {
            const float2 bv = *(const float2*)(bias + c0);
            v01.x += bv.x; v01.y += bv.y;
            v23.x += bv.x; v23.y += bv.y;
        }
        *(float2*)(C + (r0 + rb + gid)     * CDIM + c0) = v01;
        *(float2*)(C + (r0 + rb + gid + 8) * CDIM + c0) = v23;
    }
}

// ---------------------------------------------------------------------------
// Fused kernel: dual GEMM + E1-E5 (E0/E6 evicted). Writes y to g_y.
// ---------------------------------------------------------------------------
__global__ __launch_bounds__(NTHR, 2)
void fused_kernel(const float* __restrict__ k,
                  const float* __restrict__ pos, const int* __restrict__ mask,
                  const float* __restrict__ Wp1, const float* __restrict__ bp1,
                  const float* __restrict__ Wp2, const float* __restrict__ bp2,
                  const float* __restrict__ Wa1, const float* __restrict__ ba1,
                  const float* __restrict__ Wa2, const float* __restrict__ ba2)
{
    extern __shared__ float sm[];
    float* sm_big  = sm;                         // A-stage -> s1/ai/logits
    float* sm_res2 = sm_big + RPC * SKS;         // s2 -> vv
    float* sm_h    = sm_big + BIGF;              // pos hidden -> attn hidden
    float* sm_qp   = sm_h   + RPC * HS;          // q_ rows (from g_qp)
    float* sm_pos  = sm_qp  + TPC * SKS;
    int*   sm_mask = (int*)(sm_pos + RPC * 4);

    const int tid = threadIdx.x;
    const int tq  = blockIdx.x * TPC;
    const int r0g = tq * MTOK;

    // ---- stage: k rows k-permuted; q_ rows; pos; mask ---------------------
    {
        const float* kp = k + (long)r0g * CDIM;
#pragma unroll
        for (int rep = 0; rep < 4; rep++) {
            const int idx = tid + rep * NTHR;          // RPC*64 = 2048
            const int m = idx >> 6, c4 = idx & 63;
            float4 v = __ldg((const float4*)(kp + m * CDIM) + c4);
            const int kk  = c4 * 4;
            const int off = m * AST + (kk & ~7) + ((kk & 4) ? 1 : 0);
            sm_big[off + 0] = v.x;
            sm_big[off + 2] = v.y;
            sm_big[off + 4] = v.z;
            sm_big[off + 6] = v.w;
        }
        if (tid < TPC * 64) {
            const int t = tid >> 6, c4 = tid & 63;
            float4 v = *(const float4*)(g_qp + (long)(tq + t) * CDIM + c4 * 4);
            *(float4*)(sm_qp + t * SKS + c4 * 4) = v;
        }
        if (tid < RPC) {
            float4 pv = __ldg((const float4*)pos + (r0g + tid));
            *(float4*)(sm_pos + tid * 4) = pv;
            sm_mask[tid] = __ldg(mask + r0g + tid);
        }
    }
    __syncthreads();

    // ---- dual GEMM (3xTF32, fragment-ordered B): s1 = k@Ws, s2 = k@Ws2 ----
    {
        const int wid  = tid >> 5, lane = tid & 31;
        const int gid  = lane >> 2, tig = lane & 3;
        const uint4* Bf = (wid < 8) ? g_WsFrag : g_Ws2Frag;
        const int ncb = (wid & 7) * 32;

        float d[2][4][4];
#pragma unroll
        for (int mi = 0; mi < 2; mi++)
#pragma unroll
            for (int ni = 0; ni < 4; ni++)
#pragma unroll
                for (int c = 0; c < 4; c++) d[mi][ni][c] = 0.f;

        for (int ks = 0; ks < NKSTEP; ks++) {
            const int k0 = ks * 8;
            uint4 bu[4];
#pragma unroll
            for (int ni = 0; ni < 4; ni++)
                bu[ni] = __ldg(Bf + ((ks * CDIM + ncb + ni * 8 + gid) << 2) + tig);
#pragma unroll
            for (int mi = 0; mi < 2; mi++) {
                const float2 p0 = *(const float2*)(sm_big + (mi * 16 + gid) * AST + k0 + tig * 2);
                const float2 p1 = *(const float2*)(sm_big + (mi * 16 + gid + 8) * AST + k0 + tig * 2);
                uint32_t ah[4], al[4];
                ah[0] = f2tf32(p0.x); al[0] = f2tf32(p0.x - __uint_as_float(ah[0]));
                ah[1] = f2tf32(p1.x); al[1] = f2tf32(p1.x - __uint_as_float(ah[1]));
                ah[2] = f2tf32(p0.y); al[2] = f2tf32(p0.y - __uint_as_float(ah[2]));
                ah[3] = f2tf32(p1.y); al[3] = f2tf32(p1.y - __uint_as_float(ah[3]));
#pragma unroll
                for (int ni = 0; ni < 4; ni++) {
                    mma8(d[mi][ni], ah, bu[ni].x, bu[ni].y);   // hi*hi
                    mma8(d[mi][ni], al, bu[ni].x, bu[ni].y);   // lo*hi
                    mma8(d[mi][ni], ah, bu[ni].z, bu[ni].w);   // hi*lo
                }
            }
        }
        __syncthreads();                 // A-stage dead; results may overwrite
        float* dst = (wid < 8) ? sm_big : sm_res2;
#pragma unroll
        for (int mi = 0; mi < 2; mi++)
#pragma unroll
            for (int ni = 0; ni < 4; ni++) {
                const int r0 = mi * 16 + gid;
                const int c0 = ncb + ni * 8 + 2 * tig;
                *(float2*)&dst[r0 * SKS + c0]       = make_float2(d[mi][ni][0], d[mi][ni][1]);
                *(float2*)&dst[(r0 + 8) * SKS + c0] = make_float2(d[mi][ni][2], d[mi][ni][3]);
            }
    }
    __syncthreads();

    const int cg = tid & 63;
    const int rg = tid >> 6;             // 0..7, 4 rows each

    // ---- E1: pos hidden ----------------------------------------------------
    {
        const int m  = tid >> 4;             // 0..31
        const int j2 = (tid & 15) * 2;
        const float p0 = sm_pos[m * 4 + 0], p1 = sm_pos[m * 4 + 1];
        const float p2 = sm_pos[m * 4 + 2], p3 = sm_pos[m * 4 + 3];
#pragma unroll
        for (int u = 0; u < 2; u++) {
            const int j = j2 + u;
            float h = __ldg(bp1 + j);
            h = fmaf(p0, __ldg(Wp1 +  0 + j), h);
            h = fmaf(p1, __ldg(Wp1 + 32 + j), h);
            h = fmaf(p2, __ldg(Wp1 + 64 + j), h);
            h = fmaf(p3, __ldg(Wp1 + 96 + j), h);
            sm_h[m * HS + j] = fmaxf(h, 0.f);
        }
    }
    __syncthreads();

    // ---- E2 (interchanged): posf for 4 rows, Wp2 loaded once per j --------
    {
        const int tokl = rg >> 2;
        const float qp0 = sm_qp[tokl * SKS + cg * 4 + 0];
        const float qp1 = sm_qp[tokl * SKS + cg * 4 + 1];
        const float qp2 = sm_qp[tokl * SKS + cg * 4 + 2];
        const float qp3 = sm_qp[tokl * SKS + cg * 4 + 3];
        const float4 b2 = __ldg((const float4*)(bp2 + cg * 4));
        float4 pf[4];
#pragma unroll
        for (int i = 0; i < 4; i++) pf[i] = b2;
        const float* hbase = sm_h + (rg * 4) * HS;
#pragma unroll 4
        for (int j = 0; j < HIDD; j++) {
            const float4 w = __ldg((const float4*)(Wp2 + j * CDIM + cg * 4));
#pragma unroll
            for (int i = 0; i < 4; i++) {
                const float hv = hbase[i * HS + j];
                pf[i].x = fmaf(hv, w.x, pf[i].x);
                pf[i].y = fmaf(hv, w.y, pf[i].y);
                pf[i].z = fmaf(hv, w.z, pf[i].z);
                pf[i].w = fmaf(hv, w.w, pf[i].w);
            }
        }
#pragma unroll
        for (int i = 0; i < 4; i++) {
            const int m = rg * 4 + i;
            float4 s1v = *(const float4*)(sm_big  + m * SKS + cg * 4);
            float4 s2v = *(const float4*)(sm_res2 + m * SKS + cg * 4);
            float4 ai, vv;
            ai.x = s1v.x - qp0 + pf[i].x;  vv.x = s2v.x + pf[i].x;
            ai.y = s1v.y - qp1 + pf[i].y;  vv.y = s2v.y + pf[i].y;
            ai.z = s1v.z - qp2 + pf[i].z;  vv.z = s2v.z + pf[i].z;
            ai.w = s1v.w - qp3 + pf[i].w;  vv.w = s2v.w + pf[i].w;
            *(float4*)(sm_big  + m * SKS + cg * 4) = ai;
            *(float4*)(sm_res2 + m * SKS + cg * 4) = vv;
        }
    }
    __syncthreads();

    // ---- E3: h2 = relu(ai @ Wa1 + ba1) ------------------------------------
    {
        const int m  = tid >> 4;             // 0..31
        const int jp = (tid & 15) * 2;
        float2 acc = *(const float2*)(ba1 + jp);
        const float* as = sm_big + m * SKS;
#pragma unroll 4
        for (int c2 = 0; c2 < CDIM; c2++) {
            const float a = as[c2];
            const float2 w = __ldg((const float2*)(Wa1 + c2 * HIDD + jp));
            acc.x = fmaf(a, w.x, acc.x);
            acc.y = fmaf(a, w.y, acc.y);
        }
        acc.x = fmaxf(acc.x, 0.f);
        acc.y = fmaxf(acc.y, 0.f);
        *(float2*)(sm_h + m * HS + jp) = acc;
    }
    __syncthreads();

    // ---- E4 (interchanged): logits for 4 rows, Wa2 loaded once per j ------
    {
        const float4 b2 = __ldg((const float4*)(ba2 + cg * 4));
        float4 acc[4];
#pragma unroll
        for (int i = 0; i < 4; i++) acc[i] = b2;
        const float* hbase = sm_h + (rg * 4) * HS;
#pragma unroll 4
        for (int j = 0; j < HIDD; j++) {
            const float4 w = __ldg((const float4*)(Wa2 + j * CDIM + cg * 4));
#pragma unroll
            for (int i = 0; i < 4; i++) {
                const float hv = hbase[i * HS + j];
                acc[i].x = fmaf(hv, w.x, acc[i].x);
                acc[i].y = fmaf(hv, w.y, acc[i].y);
                acc[i].z = fmaf(hv, w.z, acc[i].z);
                acc[i].w = fmaf(hv, w.w, acc[i].w);
            }
        }
#pragma unroll
        for (int i = 0; i < 4; i++) {
            const int m = rg * 4 + i;
            float4 v = acc[i];
            if (sm_mask[m] == 0) { v.x = -1e9f; v.y = -1e9f; v.z = -1e9f; v.w = -1e9f; }
            *(float4*)(sm_big + m * SKS + cg * 4) = v;
        }
    }
    __syncthreads();

    // ---- E5: softmax over M, weighted sum -> g_y (global) -----------------
    {
        const int t = tid >> 8, c = tid & 255;
        const float* lp  = sm_big  + (t * MTOK) * SKS + c;
        const float* vpp = sm_res2 + (t * MTOK) * SKS + c;
        float mx = -3.4e38f;
#pragma unroll
        for (int m = 0; m < MTOK; m++) mx = fmaxf(mx, lp[m * SKS]);
        float s = 0.f, acc = 0.f;
#pragma unroll
        for (int m = 0; m < MTOK; m++) {
            const float e = __expf(lp[m * SKS] - mx);
            s += e;
            acc = fmaf(e, vpp[m * SKS], acc);
        }
        g_y[(long)(tq + t) * CDIM + c] = acc / s;
    }
}

// ---------------------------------------------------------------------------
extern "C" void kernel_launch(void* const* d_in, const int* in_sizes, int n_in,
                              void* d_out, int out_size) {
    const float* q   = (const float*)d_in[0];
    const float* k   = (const float*)d_in[1];
    const float* pos = (const float*)d_in[2];
    const int*   mask= (const int*)  d_in[3];
    const float* Ws  = (const float*)d_in[4];
    const float* Wp1 = (const float*)d_in[5];
    const float* bp1 = (const float*)d_in[6];
    const float* Wp2 = (const float*)d_in[7];
    const float* bp2 = (const float*)d_in[8];
    const float* Wa1 = (const float*)d_in[9];
    const float* ba1 = (const float*)d_in[10];
    const float* Wa2 = (const float*)d_in[11];
    const float* ba2 = (const float*)d_in[12];
    const float* Wo  = (const float*)d_in[13];
    const float* bo  = (const float*)d_in[14];
    float* out = (float*)d_out;

    cudaFuncSetAttribute(fused_kernel,
                         cudaFuncAttributeMaxDynamicSharedMemorySize, SMEM_BYTES);

    ws2_kernel  <<<CDIM, CDIM>>>(Ws);
    frag_kernel <<<NFRAG / 256, 256>>>(Ws, Wo);
    gemm32_kernel<<<NTOK / RPC, NTHR>>>(q, nullptr, nullptr, 0);     // q_ = q@Ws
    fused_kernel<<<NTOK / TPC, NTHR, SMEM_BYTES>>>(
        k, pos, mask, Wp1, bp1, Wp2, bp2, Wa1, ba1, Wa2, ba2);
    gemm32_kernel<<<NTOK / RPC, NTHR>>>(nullptr, bo, out, 1);        // x = y@Wo + bo
}

// round 17
// speedup vs baseline: 1.4980x; 1.1138x over previous
#include <cuda_runtime.h>
#include <cstdint>

// ---------------------------------------------------------------------------
// Attention2D — Round 17 (third submit of the E3-mma kernel; R15/R16 both
// died to broker container failures with zero signal — same flake pattern
// that preceded R8 and R13 passes).
//   R14 + tensor-ized E3: h2 = relu(ai@Wa1+ba1) as 8 warps x one 16x8 mma
//   tile (K=256), A via conflict-free LDS.32 + register tf32 split, Wa1 as
//   fragment-ordered uint4 (512B-contiguous warp loads). ~11K -> ~3K wf/CTA.
// ---------------------------------------------------------------------------

#define CDIM    256
#define HIDD    32
#define MTOK    16
#define TPC     2                    // tokens per CTA (fused)
#define RPC     32                   // rows per CTA (fused & gemm)
#define SKS     260                  // result smem row stride
#define AST     264                  // A-stage row stride
#define HS      36
#define NTOK    16384
#define NTHR    512
#define NKSTEP  (CDIM / 8)
#define NFRAG   (NKSTEP * CDIM * 4)  // 32768 uint4 per 256x256 matrix
#define NFRAGA1 (NKSTEP * HIDD * 4)  // 4096 uint4 for Wa1 (256x32)

#define BIGF    (2 * RPC * SKS)
#define SMEM_FLOATS (BIGF + RPC*HS + TPC*SKS + RPC*4 + RPC)
#define SMEM_BYTES  (SMEM_FLOATS * 4)

__device__ float g_Ws2[CDIM * CDIM];
__device__ uint4 g_WsFrag [NFRAG];        // fragment-ordered Ws  (tf32 hi/lo)
__device__ uint4 g_Ws2Frag[NFRAG];        // fragment-ordered Ws2
__device__ uint4 g_WoFrag [NFRAG];        // fragment-ordered Wo
__device__ uint4 g_Wa1Frag[NFRAGA1];      // fragment-ordered Wa1
__device__ float g_qp[(long)NTOK * CDIM]; // q @ Ws
__device__ float g_y [(long)NTOK * CDIM]; // pooled output before Wo

__device__ __forceinline__ uint32_t f2tf32(float x) {
    uint32_t r;
    asm("cvt.rna.tf32.f32 %0, %1;" : "=r"(r) : "f"(x));
    return r;
}

__device__ __forceinline__ void mma8(float* d, const uint32_t* a,
                                     uint32_t b0, uint32_t b1) {
    asm volatile(
        "mma.sync.aligned.m16n8k8.row.col.f32.tf32.tf32.f32 "
        "{%0,%1,%2,%3}, {%4,%5,%6,%7}, {%8,%9}, {%0,%1,%2,%3};"
        : "+f"(d[0]), "+f"(d[1]), "+f"(d[2]), "+f"(d[3])
        : "r"(a[0]), "r"(a[1]), "r"(a[2]), "r"(a[3]), "r"(b0), "r"(b1));
}

// ---------------------------------------------------------------------------
__global__ void ws2_kernel(const float* __restrict__ Ws) {
    __shared__ float row[CDIM];
    const int r = blockIdx.x, c = threadIdx.x;
    row[c] = Ws[r * CDIM + c];
    __syncthreads();
    float acc = 0.f;
#pragma unroll 8
    for (int kk = 0; kk < CDIM; kk++)
        acc = fmaf(row[kk], __ldg(Ws + kk * CDIM + c), acc);
    g_Ws2[r * CDIM + c] = acc;
}

// Build fragment-ordered hi/lo arrays for Ws, Ws2, Wo, Wa1. (AFTER ws2.)
// Entry (ks, c, tig) holds rows r1 = ks*8+tig, r2 = r1+4 of column c:
//   uint4{ hi(B[r1][c]), hi(B[r2][c]), lo(B[r1][c]), lo(B[r2][c]) }
__global__ void frag_kernel(const float* __restrict__ Ws,
                            const float* __restrict__ Wo,
                            const float* __restrict__ Wa1) {
    const int i   = blockIdx.x * 256 + threadIdx.x;     // 0 .. 32767
    const int ks  = i >> 10;
    const int c   = (i >> 2) & 255;
    const int tig = i & 3;
    const int r1  = ks * 8 + tig, r2 = r1 + 4;

    float a1 = __ldg(Ws + r1 * CDIM + c), a2 = __ldg(Ws + r2 * CDIM + c);
    uint32_t h1 = f2tf32(a1), h2 = f2tf32(a2);
    g_WsFrag[i] = make_uint4(h1, h2, f2tf32(a1 - __uint_as_float(h1)),
                                     f2tf32(a2 - __uint_as_float(h2)));
    a1 = g_Ws2[r1 * CDIM + c]; a2 = g_Ws2[r2 * CDIM + c];
    h1 = f2tf32(a1); h2 = f2tf32(a2);
    g_Ws2Frag[i] = make_uint4(h1, h2, f2tf32(a1 - __uint_as_float(h1)),
                                      f2tf32(a2 - __uint_as_float(h2)));
    a1 = __ldg(Wo + r1 * CDIM + c); a2 = __ldg(Wo + r2 * CDIM + c);
    h1 = f2tf32(a1); h2 = f2tf32(a2);
    g_WoFrag[i] = make_uint4(h1, h2, f2tf32(a1 - __uint_as_float(h1)),
                                     f2tf32(a2 - __uint_as_float(h2)));
    if (i < NFRAGA1) {
        const int ksA = i >> 7;            // 32 cols * 4 tig = 128 per kstep
        const int j   = (i >> 2) & 31;
        const int tg  = i & 3;
        const int rA1 = ksA * 8 + tg, rA2 = rA1 + 4;
        float b1 = __ldg(Wa1 + rA1 * HIDD + j), b2 = __ldg(Wa1 + rA2 * HIDD + j);
        uint32_t g1 = f2tf32(b1), g2 = f2tf32(b2);
        g_Wa1Frag[i] = make_uint4(g1, g2, f2tf32(b1 - __uint_as_float(g1)),
                                          f2tf32(b2 - __uint_as_float(g2)));
    }
}

// ---------------------------------------------------------------------------
// Generic 3xTF32 GEMM, 32 rows/CTA, C[16384x256] = A @ B (+bias).
// mode 0: A=Aext(q), B=g_WsFrag, C=g_qp, no bias.
// mode 1: A=g_y,     B=g_WoFrag, C=Cext(out), bias=bo.
// ---------------------------------------------------------------------------
__global__ __launch_bounds__(NTHR, 2)
void gemm32_kernel(const float* __restrict__ Aext,
                   const float* __restrict__ bias,
                   float* __restrict__ Cext, int mode)
{
    __shared__ float smA[RPC * AST];             // 33,792 B
    const float* A  = (mode == 0) ? Aext : g_y;
    float*       C  = (mode == 0) ? g_qp : Cext;
    const uint4* Bf = (mode == 0) ? g_WsFrag : g_WoFrag;

    const int tid = threadIdx.x;
    const long r0 = (long)blockIdx.x * RPC;

    // stage A k-permuted (k%8: 0..3 -> even slots, 4..7 -> odd)
#pragma unroll
    for (int rep = 0; rep < 4; rep++) {
        const int idx = tid + rep * NTHR;
        const int m = idx >> 6, c4 = idx & 63;
        float4 v = __ldg((const float4*)(A + (r0 + m) * CDIM) + c4);
        const int kk  = c4 * 4;
        const int off = m * AST + (kk & ~7) + ((kk & 4) ? 1 : 0);
        smA[off + 0] = v.x;
        smA[off + 2] = v.y;
        smA[off + 4] = v.z;
        smA[off + 6] = v.w;
    }
    __syncthreads();

    const int wid = tid >> 5, lane = tid & 31;
    const int gid = lane >> 2, tig = lane & 3;
    const int rb  = (wid >> 3) * 16;     // row half: 0 or 16
    const int ncb = (wid & 7) * 32;      // 32-col block

    float d[4][4];
#pragma unroll
    for (int ni = 0; ni < 4; ni++)
#pragma unroll
        for (int c = 0; c < 4; c++) d[ni][c] = 0.f;

    for (int ks = 0; ks < NKSTEP; ks++) {
        const int k0 = ks * 8;
        const float2 p0 = *(const float2*)(smA + (rb + gid) * AST + k0 + tig * 2);
        const float2 p1 = *(const float2*)(smA + (rb + gid + 8) * AST + k0 + tig * 2);
        uint32_t ah[4], al[4];
        ah[0] = f2tf32(p0.x); al[0] = f2tf32(p0.x - __uint_as_float(ah[0]));
        ah[1] = f2tf32(p1.x); al[1] = f2tf32(p1.x - __uint_as_float(ah[1]));
        ah[2] = f2tf32(p0.y); al[2] = f2tf32(p0.y - __uint_as_float(ah[2]));
        ah[3] = f2tf32(p1.y); al[3] = f2tf32(p1.y - __uint_as_float(ah[3]));
#pragma unroll
        for (int ni = 0; ni < 4; ni++) {
            const uint4 u = __ldg(Bf + ((ks * CDIM + ncb + ni * 8 + gid) << 2) + tig);
            mma8(d[ni], ah, u.x, u.y);   // hi*hi
            mma8(d[ni], al, u.x, u.y);   // lo*hi
            mma8(d[ni], ah, u.z, u.w);   // hi*lo
        }
    }

#pragma unroll
    for (int ni = 0; ni < 4; ni++) {
        const int c0 = ncb + ni * 8 + 2 * tig;
        float2 v01 = make_float2(d[ni][0], d[ni][1]);
        float2 v23 = make_float2(d[ni][2], d[ni][3]);
        if (mode == 1) {
            const float2 bv = *(const float2*)(bias + c0);
            v01.x += bv.x; v01.y += bv.y;
            v23.x += bv.x; v23.y += bv.y;
        }
        *(float2*)(C + (r0 + rb + gid)     * CDIM + c0) = v01;
        *(float2*)(C + (r0 + rb + gid + 8) * CDIM + c0) = v23;
    }
}

// ---------------------------------------------------------------------------
// Fused kernel: dual GEMM + E1-E5 (E0/E6 evicted, E3 on mma). Writes g_y.
// ---------------------------------------------------------------------------
__global__ __launch_bounds__(NTHR, 2)
void fused_kernel(const float* __restrict__ k,
                  const float* __restrict__ pos, const int* __restrict__ mask,
                  const float* __restrict__ Wp1, const float* __restrict__ bp1,
                  const float* __restrict__ Wp2, const float* __restrict__ bp2,
                  const float* __restrict__ ba1,
                  const float* __restrict__ Wa2, const float* __restrict__ ba2)
{
    extern __shared__ float sm[];
    float* sm_big  = sm;                         // A-stage -> s1/ai/logits
    float* sm_res2 = sm_big + RPC * SKS;         // s2 -> vv
    float* sm_h    = sm_big + BIGF;              // pos hidden -> attn hidden
    float* sm_qp   = sm_h   + RPC * HS;          // q_ rows (from g_qp)
    float* sm_pos  = sm_qp  + TPC * SKS;
    int*   sm_mask = (int*)(sm_pos + RPC * 4);

    const int tid = threadIdx.x;
    const int tq  = blockIdx.x * TPC;
    const int r0g = tq * MTOK;

    // ---- stage: k rows k-permuted; q_ rows; pos; mask ---------------------
    {
        const float* kp = k + (long)r0g * CDIM;
#pragma unroll
        for (int rep = 0; rep < 4; rep++) {
            const int idx = tid + rep * NTHR;          // RPC*64 = 2048
            const int m = idx >> 6, c4 = idx & 63;
            float4 v = __ldg((const float4*)(kp + m * CDIM) + c4);
            const int kk  = c4 * 4;
            const int off = m * AST + (kk & ~7) + ((kk & 4) ? 1 : 0);
            sm_big[off + 0] = v.x;
            sm_big[off + 2] = v.y;
            sm_big[off + 4] = v.z;
            sm_big[off + 6] = v.w;
        }
        if (tid < TPC * 64) {
            const int t = tid >> 6, c4 = tid & 63;
            float4 v = *(const float4*)(g_qp + (long)(tq + t) * CDIM + c4 * 4);
            *(float4*)(sm_qp + t * SKS + c4 * 4) = v;
        }
        if (tid < RPC) {
            float4 pv = __ldg((const float4*)pos + (r0g + tid));
            *(float4*)(sm_pos + tid * 4) = pv;
            sm_mask[tid] = __ldg(mask + r0g + tid);
        }
    }
    __syncthreads();

    const int wid  = tid >> 5, lane = tid & 31;
    const int gid  = lane >> 2, tig = lane & 3;

    // ---- dual GEMM (3xTF32, fragment-ordered B): s1 = k@Ws, s2 = k@Ws2 ----
    {
        const uint4* Bf = (wid < 8) ? g_WsFrag : g_Ws2Frag;
        const int ncb = (wid & 7) * 32;

        float d[2][4][4];
#pragma unroll
        for (int mi = 0; mi < 2; mi++)
#pragma unroll
            for (int ni = 0; ni < 4; ni++)
#pragma unroll
                for (int c = 0; c < 4; c++) d[mi][ni][c] = 0.f;

        for (int ks = 0; ks < NKSTEP; ks++) {
            const int k0 = ks * 8;
            uint4 bu[4];
#pragma unroll
            for (int ni = 0; ni < 4; ni++)
                bu[ni] = __ldg(Bf + ((ks * CDIM + ncb + ni * 8 + gid) << 2) + tig);
#pragma unroll
            for (int mi = 0; mi < 2; mi++) {
                const float2 p0 = *(const float2*)(sm_big + (mi * 16 + gid) * AST + k0 + tig * 2);
                const float2 p1 = *(const float2*)(sm_big + (mi * 16 + gid + 8) * AST + k0 + tig * 2);
                uint32_t ah[4], al[4];
                ah[0] = f2tf32(p0.x); al[0] = f2tf32(p0.x - __uint_as_float(ah[0]));
                ah[1] = f2tf32(p1.x); al[1] = f2tf32(p1.x - __uint_as_float(ah[1]));
                ah[2] = f2tf32(p0.y); al[2] = f2tf32(p0.y - __uint_as_float(ah[2]));
                ah[3] = f2tf32(p1.y); al[3] = f2tf32(p1.y - __uint_as_float(ah[3]));
#pragma unroll
                for (int ni = 0; ni < 4; ni++) {
                    mma8(d[mi][ni], ah, bu[ni].x, bu[ni].y);   // hi*hi
                    mma8(d[mi][ni], al, bu[ni].x, bu[ni].y);   // lo*hi
                    mma8(d[mi][ni], ah, bu[ni].z, bu[ni].w);   // hi*lo
                }
            }
        }
        __syncthreads();                 // A-stage dead; results may overwrite
        float* dst = (wid < 8) ? sm_big : sm_res2;
#pragma unroll
        for (int mi = 0; mi < 2; mi++)
#pragma unroll
            for (int ni = 0; ni < 4; ni++) {
                const int r0 = mi * 16 + gid;
                const int c0 = ncb + ni * 8 + 2 * tig;
                *(float2*)&dst[r0 * SKS + c0]       = make_float2(d[mi][ni][0], d[mi][ni][1]);
                *(float2*)&dst[(r0 + 8) * SKS + c0] = make_float2(d[mi][ni][2], d[mi][ni][3]);
            }
    }
    __syncthreads();

    const int cg = tid & 63;
    const int rg = tid >> 6;             // 0..7, 4 rows each

    // ---- E1: pos hidden ----------------------------------------------------
    {
        const int m  = tid >> 4;             // 0..31
        const int j2 = (tid & 15) * 2;
        const float p0 = sm_pos[m * 4 + 0], p1 = sm_pos[m * 4 + 1];
        const float p2 = sm_pos[m * 4 + 2], p3 = sm_pos[m * 4 + 3];
#pragma unroll
        for (int u = 0; u < 2; u++) {
            const int j = j2 + u;
            float h = __ldg(bp1 + j);
            h = fmaf(p0, __ldg(Wp1 +  0 + j), h);
            h = fmaf(p1, __ldg(Wp1 + 32 + j), h);
            h = fmaf(p2, __ldg(Wp1 + 64 + j), h);
            h = fmaf(p3, __ldg(Wp1 + 96 + j), h);
            sm_h[m * HS + j] = fmaxf(h, 0.f);
        }
    }
    __syncthreads();

    // ---- E2 (interchanged): posf for 4 rows, Wp2 loaded once per j --------
    {
        const int tokl = rg >> 2;
        const float qp0 = sm_qp[tokl * SKS + cg * 4 + 0];
        const float qp1 = sm_qp[tokl * SKS + cg * 4 + 1];
        const float qp2 = sm_qp[tokl * SKS + cg * 4 + 2];
        const float qp3 = sm_qp[tokl * SKS + cg * 4 + 3];
        const float4 b2 = __ldg((const float4*)(bp2 + cg * 4));
        float4 pf[4];
#pragma unroll
        for (int i = 0; i < 4; i++) pf[i] = b2;
        const float* hbase = sm_h + (rg * 4) * HS;
#pragma unroll 4
        for (int j = 0; j < HIDD; j++) {
            const float4 w = __ldg((const float4*)(Wp2 + j * CDIM + cg * 4));
#pragma unroll
            for (int i = 0; i < 4; i++) {
                const float hv = hbase[i * HS + j];
                pf[i].x = fmaf(hv, w.x, pf[i].x);
                pf[i].y = fmaf(hv, w.y, pf[i].y);
                pf[i].z = fmaf(hv, w.z, pf[i].z);
                pf[i].w = fmaf(hv, w.w, pf[i].w);
            }
        }
#pragma unroll
        for (int i = 0; i < 4; i++) {
            const int m = rg * 4 + i;
            float4 s1v = *(const float4*)(sm_big  + m * SKS + cg * 4);
            float4 s2v = *(const float4*)(sm_res2 + m * SKS + cg * 4);
            float4 ai, vv;
            ai.x = s1v.x - qp0 + pf[i].x;  vv.x = s2v.x + pf[i].x;
            ai.y = s1v.y - qp1 + pf[i].y;  vv.y = s2v.y + pf[i].y;
            ai.z = s1v.z - qp2 + pf[i].z;  vv.z = s2v.z + pf[i].z;
            ai.w = s1v.w - qp3 + pf[i].w;  vv.w = s2v.w + pf[i].w;
            *(float4*)(sm_big  + m * SKS + cg * 4) = ai;
            *(float4*)(sm_res2 + m * SKS + cg * 4) = vv;
        }
    }
    __syncthreads();

    // ---- E3 (mma): h2 = relu(ai @ Wa1 + ba1), warps 0-7 -------------------
    // 8 tiles of 16x8: m0 = (wid>>2)*16, cols nj = (wid&3)*8. A from sm_big
    // (conflict-free LDS.32: bank = gid*4+tig = lane), B = g_Wa1Frag.
    {
        if (wid < 8) {
            const int m0 = (wid >> 2) * 16;
            const int nj = (wid & 3) * 8;
            float d[4] = {0.f, 0.f, 0.f, 0.f};
            for (int ks = 0; ks < NKSTEP; ks++) {
                const int k0 = ks * 8;
                const float a0 = sm_big[(m0 + gid)     * SKS + k0 + tig];
                const float a1 = sm_big[(m0 + gid + 8) * SKS + k0 + tig];
                const float a2 = sm_big[(m0 + gid)     * SKS + k0 + tig + 4];
                const float a3 = sm_big[(m0 + gid + 8) * SKS + k0 + tig + 4];
                uint32_t ah[4], al[4];
                ah[0] = f2tf32(a0); al[0] = f2tf32(a0 - __uint_as_float(ah[0]));
                ah[1] = f2tf32(a1); al[1] = f2tf32(a1 - __uint_as_float(ah[1]));
                ah[2] = f2tf32(a2); al[2] = f2tf32(a2 - __uint_as_float(ah[2]));
                ah[3] = f2tf32(a3); al[3] = f2tf32(a3 - __uint_as_float(ah[3]));
                const uint4 u = __ldg(g_Wa1Frag + ((ks * HIDD + nj + gid) << 2) + tig);
                mma8(d, ah, u.x, u.y);   // hi*hi
                mma8(d, al, u.x, u.y);   // lo*hi
                mma8(d, ah, u.z, u.w);   // hi*lo
            }
            const int j0 = nj + 2 * tig;
            const float2 bv = *(const float2*)(ba1 + j0);
            float2 r0 = make_float2(fmaxf(d[0] + bv.x, 0.f), fmaxf(d[1] + bv.y, 0.f));
            float2 r1 = make_float2(fmaxf(d[2] + bv.x, 0.f), fmaxf(d[3] + bv.y, 0.f));
            *(float2*)(sm_h + (m0 + gid)     * HS + j0) = r0;
            *(float2*)(sm_h + (m0 + gid + 8) * HS + j0) = r1;
        }
    }
    __syncthreads();

    // ---- E4 (interchanged): logits for 4 rows, Wa2 loaded once per j ------
    {
        const float4 b2 = __ldg((const float4*)(ba2 + cg * 4));
        float4 acc[4];
#pragma unroll
        for (int i = 0; i < 4; i++) acc[i] = b2;
        const float* hbase = sm_h + (rg * 4) * HS;
#pragma unroll 4
        for (int j = 0; j < HIDD; j++) {
            const float4 w = __ldg((const float4*)(Wa2 + j * CDIM + cg * 4));
#pragma unroll
            for (int i = 0; i < 4; i++) {
                const float hv = hbase[i * HS + j];
                acc[i].x = fmaf(hv, w.x, acc[i].x);
                acc[i].y = fmaf(hv, w.y, acc[i].y);
                acc[i].z = fmaf(hv, w.z, acc[i].z);
                acc[i].w = fmaf(hv, w.w, acc[i].w);
            }
        }
#pragma unroll
        for (int i = 0; i < 4; i++) {
            const int m = rg * 4 + i;
            float4 v = acc[i];
            if (sm_mask[m] == 0) { v.x = -1e9f; v.y = -1e9f; v.z = -1e9f; v.w = -1e9f; }
            *(float4*)(sm_big + m * SKS + cg * 4) = v;
        }
    }
    __syncthreads();

    // ---- E5: softmax over M, weighted sum -> g_y (global) -----------------
    {
        const int t = tid >> 8, c = tid & 255;
        const float* lp  = sm_big  + (t * MTOK) * SKS + c;
        const float* vpp = sm_res2 + (t * MTOK) * SKS + c;
        float mx = -3.4e38f;
#pragma unroll
        for (int m = 0; m < MTOK; m++) mx = fmaxf(mx, lp[m * SKS]);
        float s = 0.f, acc = 0.f;
#pragma unroll
        for (int m = 0; m < MTOK; m++) {
            const float e = __expf(lp[m * SKS] - mx);
            s += e;
            acc = fmaf(e, vpp[m * SKS], acc);
        }
        g_y[(long)(tq + t) * CDIM + c] = acc / s;
    }
}

// ---------------------------------------------------------------------------
extern "C" void kernel_launch(void* const* d_in, const int* in_sizes, int n_in,
                              void* d_out, int out_size) {
    const float* q   = (const float*)d_in[0];
    const float* k   = (const float*)d_in[1];
    const float* pos = (const float*)d_in[2];
    const int*   mask= (const int*)  d_in[3];
    const float* Ws  = (const float*)d_in[4];
    const float* Wp1 = (const float*)d_in[5];
    const float* bp1 = (const float*)d_in[6];
    const float* Wp2 = (const float*)d_in[7];
    const float* bp2 = (const float*)d_in[8];
    const float* Wa1 = (const float*)d_in[9];
    const float* ba1 = (const float*)d_in[10];
    const float* Wa2 = (const float*)d_in[11];
    const float* ba2 = (const float*)d_in[12];
    const float* Wo  = (const float*)d_in[13];
    const float* bo  = (const float*)d_in[14];
    float* out = (float*)d_out;

    cudaFuncSetAttribute(fused_kernel,
                         cudaFuncAttributeMaxDynamicSharedMemorySize, SMEM_BYTES);

    ws2_kernel  <<<CDIM, CDIM>>>(Ws);
    frag_kernel <<<NFRAG / 256, 256>>>(Ws, Wo, Wa1);
    gemm32_kernel<<<NTOK / RPC, NTHR>>>(q, nullptr, nullptr, 0);     // q_ = q@Ws
    fused_kernel<<<NTOK / TPC, NTHR, SMEM_BYTES>>>(
        k, pos, mask, Wp1, bp1, Wp2, bp2, ba1, Wa2, ba2);
    gemm32_kernel<<<NTOK / RPC, NTHR>>>(nullptr, bo, out, 1);        // x = y@Wo + bo
}